// round 13
// baseline (speedup 1.0000x reference)
#include <cuda_runtime.h>

typedef unsigned long long u64;

#define HALF     512
#define BATCH    8192
#define DEPTH    20
#define TB       16          // 16 batch columns per block (4 bq x 4 cols)
#define NTHREADS 256         // 64 row-threads x 4 batch-quad threads
#define NBLOCKS  (BATCH / TB)

// Scalar (c,s) coefs, 8B. Table permuted PER LAYER so the hot loop always
// reads slot e*64 + rt (e = pair index 0..7, rt = row-thread 0..63):
// a warp's 8 consecutive rt -> 64 consecutive bytes, broadcast over 4 bq lanes.
__device__ float2 g_cs[DEPTH * HALF];

__global__ void prep_kernel(const float* __restrict__ ang) {
    int t = blockIdx.x * blockDim.x + threadIdx.x;
    if (t >= DEPTH * HALF) return;
    const int i = t >> 9, k = t & 511;
    const int e = k >> 6, rt = k & 63;
    const int im = i % 10;
    int l, g, base;
    if (im < 4)      { l = im;          g = 1;  base = rt * 16; }
    else if (im < 8) { l = im - 4;      g = 16; base = (rt >> 4) * 256 + (rt & 15); }
    else             { l = im - 8 + 2;  g = 64; base = rt; }
    const int j0 = ((e >> l) << (l + 1)) | (e & ((1 << l) - 1));
    const int r0 = base + g * j0;
    const int s  = g << l;
    const int p  = ((r0 / (2 * s)) * s) | (r0 & (s - 1));
    float sv, cv;
    sincosf(ang[i * 512 + p], &sv, &cv);
    g_cs[i * 512 + k] = make_float2(cv, sv);
}

// ---- packed f32x2 helpers (sm_100) ----
__device__ __forceinline__ u64 pk2(float v) {
    u64 r; asm("mov.b64 %0, {%1, %1};" : "=l"(r) : "f"(v)); return r;
}
__device__ __forceinline__ u64 mul2(u64 a, u64 b) {
    u64 d; asm("mul.rn.f32x2 %0, %1, %2;" : "=l"(d) : "l"(a), "l"(b)); return d;
}
__device__ __forceinline__ u64 fma2(u64 a, u64 b, u64 c) {
    u64 d; asm("fma.rn.f32x2 %0, %1, %2, %3;" : "=l"(d) : "l"(a), "l"(b), "l"(c)); return d;
}
__device__ __forceinline__ void rot(u64& x0, u64& x1, u64 cc, u64 ss, u64 ns) {
    const u64 y0 = fma2(cc, x0, mul2(ss, x1));
    const u64 y1 = fma2(ns, x0, mul2(cc, x1));
    x0 = y0; x1 = y1;
}

// NL layers at reg-strides 2^(LB)..; 8 pairs per layer on 16 u64 x 2 arrays
// (4 independent FMA chains per rotation), dist-1 coef prefetch.
template<int NL, int LB>
__device__ __forceinline__ void passG(u64* Xa, u64* Xb, const float2* __restrict__ lt) {
    float2 cf[4];
#pragma unroll
    for (int t = 0; t < 4; ++t) cf[t] = __ldg(lt + t * 64);
    const int Q = NL * 2;
#pragma unroll
    for (int v = 0; v < Q; ++v) {
        const int l = LB + (v >> 1);
        float2 nf[4];
        if (v < Q - 1) {
            const int li2 = (v + 1) >> 1, h2 = (v + 1) & 1;
#pragma unroll
            for (int t = 0; t < 4; ++t)
                nf[t] = __ldg(lt + li2 * 512 + (h2 * 4 + t) * 64);
        }
#pragma unroll
        for (int t = 0; t < 4; ++t) {
            const int e  = (v & 1) * 4 + t;
            const int sg = 1 << l;
            const int j  = ((e >> l) << (l + 1)) | (e & (sg - 1));
            const u64 cc = pk2(cf[t].x);
            const u64 ss = pk2(cf[t].y);
            const u64 ns = ss ^ 0x8000000080000000ULL;
            rot(Xa[j], Xa[j + sg], cc, ss, ns);
            rot(Xb[j], Xb[j + sg], cc, ss, ns);
        }
#pragma unroll
        for (int t = 0; t < 4; ++t) cf[t] = nf[t];
    }
}

// Tile swizzle, 16B units: addr(row,bq) = ((row<<2)|bq) ^ ((row>>4)&7)
// (XOR touches only low-3 bits). Enumerated 4 lanes/bank-quad (4-phase
// minimum for 512B accesses) in all three layouts; bijective. Folded:
#define ADRA(j) (baseA + (((j) >> 1) << 3) + (((j) & 1) ? kA4 : kA0))   // row=rt*16+j
#define ADRB(j) (baseB + (j) * 64 + (mB ^ ((j) & 7)))                   // row=C+(rt&15)+16j
#define ADRC(j) (baseC + (j) * 256 + (mC ^ (((j) & 1) << 2)))           // row=rt+64j

extern "C" __global__ void __launch_bounds__(NTHREADS, 2)
butterfly_kernel(const float* __restrict__ X, float* __restrict__ Y)
{
    extern __shared__ ulonglong2 tile[];   // 1024 rows x 4 bq x 16B = 64 KB

    const int bq = threadIdx.x & 3;        // batch-quad (4 cols)
    const int rt = threadIdx.x >> 2;       // row-thread 0..63
    const long long bb = (long long)blockIdx.x * TB + bq * 4;

    const int baseA = rt * 64;
    const int kA0   = bq ^ (rt & 7);
    const int kA4   = (4 | bq) ^ (rt & 7);
    const int baseB = (rt >> 4) * 1024 + ((rt & 15) >> 1) * 8;
    const int mB    = ((rt & 1) << 2) | bq;
    const int baseC = (rt >> 1) * 8;
    const int mC    = (((rt & 1) << 2) | bq) ^ ((rt >> 4) & 7);

    u64 Xa[16], Xb[16];                    // 16 rows x 4 batch columns

    // ---- load, layout gA (reg j = row rt*16+j); .cg keeps L1 for coefs ----
#pragma unroll
    for (int j = 0; j < 16; ++j) {
        const float4 v = __ldcg(
            reinterpret_cast<const float4*>(X + (long long)(rt * 16 + j) * BATCH + bb));
        asm("mov.b64 %0, {%2, %3}; mov.b64 %1, {%4, %5};"
            : "=l"(Xa[j]), "=l"(Xb[j]) : "f"(v.x), "f"(v.y), "f"(v.z), "f"(v.w));
    }

    const float2* lt = g_cs + rt;

#define XW(AD) do { __syncthreads(); _Pragma("unroll")                        \
    for (int j = 0; j < 16; ++j) tile[AD(j)] = make_ulonglong2(Xa[j], Xb[j]); \
    __syncthreads(); } while (0)
#define XR(AD) do { _Pragma("unroll")                                         \
    for (int j = 0; j < 16; ++j) { const ulonglong2 v = tile[AD(j)];          \
        Xa[j] = v.x; Xb[j] = v.y; } } while (0)

    passG<4, 0>(Xa, Xb, lt + 0 * 512);     // layers 0-3   (strides 1..8,   gA)
    XW(ADRA); XR(ADRB);
    passG<4, 0>(Xa, Xb, lt + 4 * 512);     // layers 4-7   (strides 16..128, gB)
    XW(ADRB); XR(ADRC);
    passG<2, 2>(Xa, Xb, lt + 8 * 512);     // layers 8-9   (strides 256,512, gC)
    XW(ADRC); XR(ADRA);
    passG<4, 0>(Xa, Xb, lt + 10 * 512);    // layers 10-13 (gA)
    XW(ADRA); XR(ADRB);
    passG<4, 0>(Xa, Xb, lt + 14 * 512);    // layers 14-17 (gB)
    XW(ADRB); XR(ADRC);
    passG<2, 2>(Xa, Xb, lt + 18 * 512);    // layers 18-19 (gC)

    // ---- store, layout gC (reg j = row rt+64j): 512B contiguous per warp ----
#pragma unroll
    for (int j = 0; j < 16; ++j) {
        float x, y, z, w;
        asm("mov.b64 {%0, %1}, %4; mov.b64 {%2, %3}, %5;"
            : "=f"(x), "=f"(y), "=f"(z), "=f"(w) : "l"(Xa[j]), "l"(Xb[j]));
        __stcg(reinterpret_cast<float4*>(Y + (long long)(rt + 64 * j) * BATCH + bb),
               make_float4(x, y, z, w));
    }
}

extern "C" void kernel_launch(void* const* d_in, const int* in_sizes, int n_in,
                              void* d_out, int out_size)
{
    const float* X = (const float*)d_in[0];
    const float* A = (const float*)d_in[1];
    if (n_in >= 2 && in_sizes[0] < in_sizes[1]) {   // defensive: X is the big one
        const float* t = X; X = A; A = t;
    }
    float* Y = (float*)d_out;

    cudaFuncSetAttribute(butterfly_kernel,
                         cudaFuncAttributeMaxDynamicSharedMemorySize, 65536);

    prep_kernel<<<(DEPTH * HALF + 255) / 256, 256>>>(A);
    butterfly_kernel<<<NBLOCKS, NTHREADS, 65536>>>(X, Y);
}

// round 14
// speedup vs baseline: 1.1182x; 1.1182x over previous
#include <cuda_runtime.h>

typedef unsigned long long u64;

#define HALF     512
#define BATCH    8192
#define DEPTH    20
#define TB       16          // batch columns per block (4 bq threads x 4 cols)
#define NTHREADS 128         // 32 row-threads x 4 batch-quad threads
#define NBLOCKS  (BATCH / TB)

// Scalar (c, s) coefficients, 8B each. P1-type layers (l%10 < 5) stored
// PERMUTED: natural pair p -> slot (p&15)*32 + (p>>4), so BOTH pass types
// address coefs as m*32 + rt; a warp's 8 consecutive rt values read 64
// consecutive bytes, broadcast across the 4 bq lanes.
__device__ float2 g_cs[DEPTH * HALF];

__global__ void sincos_kernel(const float* __restrict__ ang) {
    int i = blockIdx.x * blockDim.x + threadIdx.x;
    if (i < DEPTH * HALF) {
        const int l = i / HALF;
        const int p = i % HALF;
        float s, c;
        sincosf(ang[i], &s, &c);
        const int slot = ((l % 10) < 5) ? ((p & 15) * 32 + (p >> 4)) : p;
        g_cs[l * HALF + slot] = make_float2(c, s);
    }
}

// ---- packed f32x2 helpers (sm_100) ----
__device__ __forceinline__ u64 pk2(float v) {
    u64 r; asm("mov.b64 %0, {%1, %1};" : "=l"(r) : "f"(v)); return r;
}
__device__ __forceinline__ u64 mul2(u64 a, u64 b) {
    u64 d; asm("mul.rn.f32x2 %0, %1, %2;" : "=l"(d) : "l"(a), "l"(b)); return d;
}
__device__ __forceinline__ u64 fma2(u64 a, u64 b, u64 c) {
    u64 d; asm("fma.rn.f32x2 %0, %1, %2, %3;" : "=l"(d) : "l"(a), "l"(b), "l"(c)); return d;
}

// Givens rotation on one packed pair: y0 = c*x0 + s*x1 ; y1 = -s*x0 + c*x1
__device__ __forceinline__ void rot(u64& x0, u64& x1, u64 cc, u64 ss, u64 ns) {
    const u64 y0 = fma2(cc, x0, mul2(ss, x1));
    const u64 y1 = fma2(ns, x0, mul2(cc, x1));
    x0 = y0; x1 = y1;
}

// Five butterfly levels fully in registers on 4 batch columns (Xa, Xb -> 4
// independent FMA chains per rotation). Flattened into 20 q-steps with a
// dist-1 pipelined coefficient stream.
// Coef slot = m*32 + rt; pairs (j, j+2^l), j = ((m>>l)<<(l+1)) | (m & (2^l-1)).
__device__ __forceinline__ void pass5(u64* Xa, u64* Xb, const float2* __restrict__ lt) {
    float2 cf[4];
#pragma unroll
    for (int t = 0; t < 4; ++t) cf[t] = __ldg(lt + t * 32);

#pragma unroll
    for (int u = 0; u < 20; ++u) {
        const int l = u >> 2;
        const int q = u & 3;
        float2 nf[4];
        if (u < 19) {
            const int l2 = (u + 1) >> 2;
            const int q2 = (u + 1) & 3;
#pragma unroll
            for (int t = 0; t < 4; ++t)
                nf[t] = __ldg(lt + l2 * HALF + (q2 * 4 + t) * 32);
        }
#pragma unroll
        for (int t = 0; t < 4; ++t) {
            const int m  = q * 4 + t;
            const int sg = 1 << l;
            const int j  = ((m >> l) << (l + 1)) | (m & (sg - 1));
            const u64 cc = pk2(cf[t].x);
            const u64 ss = pk2(cf[t].y);
            const u64 ns = ss ^ 0x8000000080000000ULL;
            rot(Xa[j], Xa[j + sg], cc, ss, ns);
            rot(Xb[j], Xb[j + sg], cc, ss, ns);
        }
#pragma unroll
        for (int t = 0; t < 4; ++t) cf[t] = nf[t];
    }
}

// Smem swizzle in 16B units (hardware-verified in R5/R10):
// addr(row,bq) = ((row ^ ((row>>5)&1)) << 2) | bq. For warp = 8 rt x 4 bq,
// both exchange groupings hit each 128B bank-group with exactly 4 lanes ->
// 512B warp accesses at the 4-phase minimum. Bijective.
#define ADRA(j) (baseA + (((j) ^ eA) << 2))                 // row = rt*32+j
#define ADRB(j) ((j) * 128 + (((j) & 1) ? baseB1 : baseB0)) // row = rt+32j

extern "C" __global__ void __launch_bounds__(NTHREADS, 2)
butterfly_kernel(const float* __restrict__ X, float* __restrict__ Y)
{
    extern __shared__ ulonglong2 tile[];   // 1024 rows x 4 bq x 16B = 64 KB

    const int bq = threadIdx.x & 3;        // batch-quad (4 cols) 0..3
    const int rt = threadIdx.x >> 2;       // row-thread 0..31
    const long long bb = (long long)blockIdx.x * TB + bq * 4;

    const int eA     = rt & 1;
    const int baseA  = rt * 128 + bq;
    const int baseB0 = (rt << 2) + bq;
    const int baseB1 = ((rt ^ 1) << 2) + bq;

    u64 Xa[32], Xb[32];                    // 32 rows x 4 batch columns

    // Load, layout A (reg j = row rt*32+j); .cg keeps L1 for the coef table.
#pragma unroll
    for (int j = 0; j < 32; ++j) {
        const float4 v = __ldcg(
            reinterpret_cast<const float4*>(X + (long long)(rt * 32 + j) * BATCH + bb));
        asm("mov.b64 %0, {%2, %3}; mov.b64 %1, {%4, %5};"
            : "=l"(Xa[j]), "=l"(Xb[j]) : "f"(v.x), "f"(v.y), "f"(v.z), "f"(v.w));
    }

    // ---- warm the 80KB coef table into L1 (flushed every launch). 40 bulk
    // 16B nc-loads per thread, overlapped with the X-load latency above. ----
    {
        const ulonglong2* tb = reinterpret_cast<const ulonglong2*>(g_cs) + threadIdx.x;
#pragma unroll 4
        for (int i = 0; i < 40; ++i) {
            u64 d0, d1;
            asm volatile("ld.global.nc.v2.b64 {%0, %1}, [%2];"
                         : "=l"(d0), "=l"(d1) : "l"(tb + i * NTHREADS));
        }
    }

    const float2* lt = g_cs + rt;

#pragma unroll 1
    for (int sp = 0; sp < 2; ++sp) {
        // layers sp*10 .. sp*10+4 (register strides 1..16 in layout A)
        pass5(Xa, Xb, lt + (sp * 10) * HALF);

        // exchange A -> B
        __syncthreads();
#pragma unroll
        for (int j = 0; j < 32; ++j) tile[ADRA(j)] = make_ulonglong2(Xa[j], Xb[j]);
        __syncthreads();
#pragma unroll
        for (int j = 0; j < 32; ++j) {
            const ulonglong2 v = tile[ADRB(j)];
            Xa[j] = v.x; Xb[j] = v.y;
        }

        // layers sp*10+5 .. sp*10+9 (strides 32..512 in layout B)
        pass5(Xa, Xb, lt + (sp * 10 + 5) * HALF);

        if (sp == 0) {
            // exchange B -> A
            __syncthreads();
#pragma unroll
            for (int j = 0; j < 32; ++j) tile[ADRB(j)] = make_ulonglong2(Xa[j], Xb[j]);
            __syncthreads();
#pragma unroll
            for (int j = 0; j < 32; ++j) {
                const ulonglong2 v = tile[ADRA(j)];
                Xa[j] = v.x; Xb[j] = v.y;
            }
        }
    }

    // Store, layout B (reg j = row rt+32j), .cg to bypass L1.
#pragma unroll
    for (int j = 0; j < 32; ++j) {
        float x, y, z, w;
        asm("mov.b64 {%0, %1}, %4; mov.b64 {%2, %3}, %5;"
            : "=f"(x), "=f"(y), "=f"(z), "=f"(w) : "l"(Xa[j]), "l"(Xb[j]));
        __stcg(reinterpret_cast<float4*>(Y + (long long)(rt + 32 * j) * BATCH + bb),
               make_float4(x, y, z, w));
    }
}

extern "C" void kernel_launch(void* const* d_in, const int* in_sizes, int n_in,
                              void* d_out, int out_size)
{
    const float* X = (const float*)d_in[0];
    const float* A = (const float*)d_in[1];
    if (n_in >= 2 && in_sizes[0] < in_sizes[1]) {   // defensive: X is the big one
        const float* t = X; X = A; A = t;
    }
    float* Y = (float*)d_out;

    cudaFuncSetAttribute(butterfly_kernel,
                         cudaFuncAttributeMaxDynamicSharedMemorySize, 65536);

    sincos_kernel<<<(DEPTH * HALF + 255) / 256, 256>>>(A);
    butterfly_kernel<<<NBLOCKS, NTHREADS, 65536>>>(X, Y);
}